// round 2
// baseline (speedup 1.0000x reference)
#include <cuda_runtime.h>
#include <math.h>

// Problem constants
#define BB 2
#define SS 2048
#define DD 768
#define HH 12
#define HDIM 64
#define NT (BB*SS)      // 4096 tokens
#define NBH (BB*HH)     // 24 (batch*heads)

// Scratch (static device globals -- no allocation allowed)
__device__ float g_q[NBH * SS * HDIM];     // [b,h,s,hd]
__device__ float g_k[NBH * SS * HDIM];
__device__ float g_v[NBH * SS * HDIM];
__device__ float g_att[NT * DD];           // [b,s,d] attention output

// ---------------------------------------------------------------------------
// Tiled fp32 GEMM:  out[r,c] = sum_k A[r,k] * W[k,c] + bias[c]
// M=NT=4096, N=K=DD=768 fixed. 64x64 block tile, K-tile 16, 256 threads,
// 4x4 per-thread micro tile. QKV_LAYOUT=1 scatters output to [b,h,s,hd].
// ---------------------------------------------------------------------------
#define GBM 64
#define GBN 64
#define GBK 16

template<int QKV_LAYOUT>
__global__ __launch_bounds__(256)
void gemm_bias(const float* __restrict__ A, const float* __restrict__ W,
               const float* __restrict__ bias, float* __restrict__ out)
{
    __shared__ float sA[GBK][GBM + 4];   // [k][m] (A transposed in smem)
    __shared__ float sB[GBK][GBN + 4];   // [k][n]

    const int tid = threadIdx.x;
    const int tx = tid & 15;          // 0..15 (n direction)
    const int ty = tid >> 4;          // 0..15 (m direction)
    const int row0 = blockIdx.x * GBM;
    const int col0 = blockIdx.y * GBN;

    // A load: each thread one float4 along k. 64 rows x 16 k / 256 thr.
    const int a_r = tid >> 2;             // 0..63
    const int a_k = (tid & 3) << 2;       // 0,4,8,12
    // B load: each thread one float4 along n. 16 k x 64 n / 256 thr.
    const int b_k = tid >> 4;             // 0..15
    const int b_c = (tid & 15) << 2;      // 0..60

    float acc[4][4] = {};

    for (int k0 = 0; k0 < DD; k0 += GBK) {
        float4 av = *(const float4*)(A + (size_t)(row0 + a_r) * DD + k0 + a_k);
        sA[a_k + 0][a_r] = av.x;
        sA[a_k + 1][a_r] = av.y;
        sA[a_k + 2][a_r] = av.z;
        sA[a_k + 3][a_r] = av.w;
        *(float4*)&sB[b_k][b_c] =
            *(const float4*)(W + (size_t)(k0 + b_k) * DD + col0 + b_c);
        __syncthreads();

        #pragma unroll
        for (int kk = 0; kk < GBK; kk++) {
            float4 a4 = *(float4*)&sA[kk][ty << 2];
            float4 b4 = *(float4*)&sB[kk][tx << 2];
            float ar[4] = {a4.x, a4.y, a4.z, a4.w};
            float br[4] = {b4.x, b4.y, b4.z, b4.w};
            #pragma unroll
            for (int i = 0; i < 4; i++)
                #pragma unroll
                for (int j = 0; j < 4; j++)
                    acc[i][j] += ar[i] * br[j];
        }
        __syncthreads();
    }

    #pragma unroll
    for (int i = 0; i < 4; i++) {
        const int r = row0 + (ty << 2) + i;
        #pragma unroll
        for (int j = 0; j < 4; j++) {
            const int c = col0 + (tx << 2) + j;
            float v = acc[i][j] + bias[c];
            if (QKV_LAYOUT) {
                // r = b*S + s ; c = h*HD + hd  ->  out[((b*H+h)*S+s)*HD + hd]
                const int b_ = r >> 11;           // S = 2048
                const int s_ = r & (SS - 1);
                const int h_ = c >> 6;            // HD = 64
                const int hd_ = c & 63;
                out[(((size_t)(b_ * HH + h_) * SS + s_) << 6) + hd_] = v;
            } else {
                out[(size_t)r * DD + c] = v;
            }
        }
    }
}

// ---------------------------------------------------------------------------
// Flash attention, causal, fp32. One block per (q-tile, b*h).
// 64x64 tiles, 256 threads (16x16), 4x4 score micro tile per thread.
// Only k-tiles j <= q-tile are processed (causal skip).
// ---------------------------------------------------------------------------
#define ATILE 64
#define APAD  (ATILE + 4)
#define ATTN_SMEM (4 * 64 * APAD * 4)   // 4 arrays x 64 x 68 floats = 69632 B

__global__ __launch_bounds__(256)
void attn_kernel(const float* __restrict__ Q, const float* __restrict__ K,
                 const float* __restrict__ V, float* __restrict__ Oo)
{
    extern __shared__ float sm[];
    float (*sQt)[APAD] = (float(*)[APAD])(sm);                  // [d][row]
    float (*sKt)[APAD] = (float(*)[APAD])(sm + 1 * 64 * APAD);  // [d][col]
    float (*sV )[APAD] = (float(*)[APAD])(sm + 2 * 64 * APAD);  // [k][d]
    float (*sPt)[APAD] = (float(*)[APAD])(sm + 3 * 64 * APAD);  // [k][row]

    const int tid = threadIdx.x;
    const int tx = tid & 15;    // score-col / out-d group
    const int ty = tid >> 4;    // score-row group
    const int qt = blockIdx.x;  // 0..31
    const int bh = blockIdx.y;  // 0..23

    const float* Qb = Q + (size_t)bh * SS * HDIM;
    const float* Kb = K + (size_t)bh * SS * HDIM;
    const float* Vb = V + (size_t)bh * SS * HDIM;

    // Load Q tile transposed: sQt[d][row]
    #pragma unroll
    for (int l = 0; l < 4; l++) {
        const int lin = tid + l * 256;
        const int r = lin >> 4;
        const int d0 = (lin & 15) << 2;
        float4 v4 = *(const float4*)(Qb + (size_t)(qt * ATILE + r) * HDIM + d0);
        sQt[d0 + 0][r] = v4.x;
        sQt[d0 + 1][r] = v4.y;
        sQt[d0 + 2][r] = v4.z;
        sQt[d0 + 3][r] = v4.w;
    }

    float mrow[4], lrow[4], o[4][4];
    #pragma unroll
    for (int i = 0; i < 4; i++) {
        mrow[i] = -1e30f;
        lrow[i] = 0.0f;
        #pragma unroll
        for (int j = 0; j < 4; j++) o[i][j] = 0.0f;
    }

    for (int jt = 0; jt <= qt; jt++) {
        __syncthreads();   // protect sKt/sV/sPt from previous iteration readers

        // Load K tile transposed + V tile direct
        #pragma unroll
        for (int l = 0; l < 4; l++) {
            const int lin = tid + l * 256;
            const int r = lin >> 4;
            const int d0 = (lin & 15) << 2;
            float4 kv = *(const float4*)(Kb + (size_t)(jt * ATILE + r) * HDIM + d0);
            sKt[d0 + 0][r] = kv.x;
            sKt[d0 + 1][r] = kv.y;
            sKt[d0 + 2][r] = kv.z;
            sKt[d0 + 3][r] = kv.w;
            *(float4*)&sV[r][d0] =
                *(const float4*)(Vb + (size_t)(jt * ATILE + r) * HDIM + d0);
        }
        __syncthreads();

        // Scores: sc[i][j] = Q[row_i] . K[col_j]
        float sc[4][4] = {};
        #pragma unroll 16
        for (int dd = 0; dd < 64; dd++) {
            float4 a4 = *(float4*)&sQt[dd][ty << 2];
            float4 b4 = *(float4*)&sKt[dd][tx << 2];
            float ar[4] = {a4.x, a4.y, a4.z, a4.w};
            float br[4] = {b4.x, b4.y, b4.z, b4.w};
            #pragma unroll
            for (int i = 0; i < 4; i++)
                #pragma unroll
                for (int j = 0; j < 4; j++)
                    sc[i][j] += ar[i] * br[j];
        }

        const bool diag = (jt == qt);
        const float scale = 0.125f;   // 1/sqrt(64)

        #pragma unroll
        for (int i = 0; i < 4; i++) {
            float v[4];
            #pragma unroll
            for (int j = 0; j < 4; j++) {
                float val = sc[i][j] * scale;
                if (diag) {
                    const int qr = (ty << 2) + i;
                    const int kc = (tx << 2) + j;
                    if (kc > qr) val = -1e30f;
                }
                v[j] = val;
            }
            // Row max across the 16 tx threads (same ty -> same warp half)
            float tm = fmaxf(fmaxf(v[0], v[1]), fmaxf(v[2], v[3]));
            #pragma unroll
            for (int off = 8; off; off >>= 1)
                tm = fmaxf(tm, __shfl_xor_sync(0xffffffffu, tm, off));
            const float nm = fmaxf(mrow[i], tm);
            const float corr = __expf(mrow[i] - nm);
            float p[4], ps = 0.0f;
            #pragma unroll
            for (int j = 0; j < 4; j++) { p[j] = __expf(v[j] - nm); ps += p[j]; }
            #pragma unroll
            for (int off = 8; off; off >>= 1)
                ps += __shfl_xor_sync(0xffffffffu, ps, off);
            lrow[i] = lrow[i] * corr + ps;
            mrow[i] = nm;
            #pragma unroll
            for (int j = 0; j < 4; j++) o[i][j] *= corr;
            #pragma unroll
            for (int j = 0; j < 4; j++)
                sPt[(tx << 2) + j][(ty << 2) + i] = p[j];
        }
        __syncthreads();

        // O += P @ V  (o cols are hd, indexed by tx)
        #pragma unroll 16
        for (int kk = 0; kk < 64; kk++) {
            float4 a4 = *(float4*)&sPt[kk][ty << 2];
            float4 b4 = *(float4*)&sV[kk][tx << 2];
            float ar[4] = {a4.x, a4.y, a4.z, a4.w};
            float br[4] = {b4.x, b4.y, b4.z, b4.w};
            #pragma unroll
            for (int i = 0; i < 4; i++)
                #pragma unroll
                for (int j = 0; j < 4; j++)
                    o[i][j] += ar[i] * br[j];
        }
    }

    // Epilogue: normalize and write [b,s,h*HD+hd]
    const int b_ = bh / HH;
    const int h_ = bh % HH;
    #pragma unroll
    for (int i = 0; i < 4; i++) {
        const float inv = 1.0f / lrow[i];
        const int s_ = qt * ATILE + (ty << 2) + i;
        float4 ov = make_float4(o[i][0] * inv, o[i][1] * inv,
                                o[i][2] * inv, o[i][3] * inv);
        const size_t idx = ((size_t)(b_ * SS + s_)) * DD + h_ * HDIM + (tx << 2);
        *(float4*)(Oo + idx) = ov;
    }
}

// ---------------------------------------------------------------------------
// Launch
// ---------------------------------------------------------------------------
extern "C" void kernel_launch(void* const* d_in, const int* in_sizes, int n_in,
                              void* d_out, int out_size)
{
    (void)n_in; (void)in_sizes; (void)out_size;

    const float* x  = (const float*)d_in[0];
    // d_in[1] = mask (causal, implied by kernel structure)
    const float* wq = (const float*)d_in[2];
    const float* bq = (const float*)d_in[3];
    const float* wk = (const float*)d_in[4];
    const float* bk = (const float*)d_in[5];
    const float* wv = (const float*)d_in[6];
    const float* bv = (const float*)d_in[7];
    const float* wo = (const float*)d_in[8];
    const float* bo = (const float*)d_in[9];
    float* out = (float*)d_out;

    // One-time host-side setup (no stream ops; deterministic per-call work)
    static float *q = nullptr, *k = nullptr, *v = nullptr, *att = nullptr;
    if (!q) {
        cudaGetSymbolAddress((void**)&q,   g_q);
        cudaGetSymbolAddress((void**)&k,   g_k);
        cudaGetSymbolAddress((void**)&v,   g_v);
        cudaGetSymbolAddress((void**)&att, g_att);
        cudaFuncSetAttribute(attn_kernel,
                             cudaFuncAttributeMaxDynamicSharedMemorySize,
                             ATTN_SMEM);
    }

    dim3 gg(NT / GBM, DD / GBN);   // 64 x 12
    gemm_bias<1><<<gg, 256>>>(x, wq, bq, q);
    gemm_bias<1><<<gg, 256>>>(x, wk, bk, k);
    gemm_bias<1><<<gg, 256>>>(x, wv, bv, v);

    dim3 ag(SS / ATILE, NBH);      // 32 x 24
    attn_kernel<<<ag, 256, ATTN_SMEM>>>(q, k, v, att);

    gemm_bias<0><<<gg, 256>>>(att, wo, bo, out);
}

// round 4
// speedup vs baseline: 1.0097x; 1.0097x over previous
#include <cuda_runtime.h>
#include <cuda_fp16.h>
#include <mma.h>
#include <math.h>
#include <stdint.h>

using namespace nvcuda;

// Problem constants
#define BB 2
#define SS 2048
#define DD 768
#define HH 12
#define HDIM 64
#define NT (BB*SS)      // 4096 tokens
#define NBH (BB*HH)     // 24

// ---------------------------------------------------------------------------
// Device scratch
// ---------------------------------------------------------------------------
__device__ __half g_xh[(size_t)NT * DD];      // x in fp16
__device__ __half g_ah[(size_t)NT * DD];      // attention out in fp16
__device__ __half g_wqh[(size_t)DD * DD];     // W^T in fp16: [n][k]
__device__ __half g_wkh[(size_t)DD * DD];
__device__ __half g_wvh[(size_t)DD * DD];
__device__ __half g_woh[(size_t)DD * DD];
__device__ float g_q[(size_t)NT * DD];        // [b,s,d]
__device__ float g_k[(size_t)NT * DD];
__device__ float g_v[(size_t)NT * DD];
__device__ float g_att[(size_t)NT * DD];

// ---------------------------------------------------------------------------
// conv_half: fp32 -> fp16, same layout. One float4 per thread.
// ---------------------------------------------------------------------------
__global__ __launch_bounds__(256)
void conv_half(const float* __restrict__ src, __half* __restrict__ dst)
{
    const int i = blockIdx.x * 256 + threadIdx.x;   // over NT*DD/4
    float4 v = ((const float4*)src)[i];
    __half2 h0 = __floats2half2_rn(v.x, v.y);
    __half2 h1 = __floats2half2_rn(v.z, v.w);
    ((__half2*)dst)[i * 2 + 0] = h0;
    ((__half2*)dst)[i * 2 + 1] = h1;
}

// ---------------------------------------------------------------------------
// conv_wh: fp32 W [k][n] -> fp16 W^T [n][k] (transpose via smem tile)
// ---------------------------------------------------------------------------
__global__ __launch_bounds__(256)
void conv_wh(const float* __restrict__ w, __half* __restrict__ dst)
{
    __shared__ float t[32][33];
    const int kb = blockIdx.x * 32, nb = blockIdx.y * 32;
    const int tx = threadIdx.x & 31, ty = threadIdx.x >> 5;   // 32 x 8
    #pragma unroll
    for (int i = 0; i < 32; i += 8)
        t[ty + i][tx] = w[(size_t)(kb + ty + i) * DD + nb + tx];
    __syncthreads();
    #pragma unroll
    for (int i = 0; i < 32; i += 8)
        dst[(size_t)(nb + ty + i) * DD + kb + tx] = __float2half_rn(t[tx][ty + i]);
}

// ---------------------------------------------------------------------------
// WMMA fp16 GEMM: out[m,n] = sum_k A[m,k]*B[n,k] + bias[n]
// A: [NT][768] half, B: [768][768] half (row n holds W[:,n]).
// CTA 128x128, K-tile 32, 8 warps in 2(m)x4(n), warp tile 64x32.
// ---------------------------------------------------------------------------
#define TM 128
#define TN 128
#define TK 32
#define LDA 40                       // smem half pitch (padded)
#define NKT (DD / TK)                // 24
#define GEMM_SMEM (TM * 132 * 4)     // 67584 (epilogue fp32 staging dominates)

__global__ __launch_bounds__(256)
void gemm_wmma(const __half* __restrict__ A, const __half* __restrict__ B,
               const float* __restrict__ bias, float* __restrict__ out)
{
    extern __shared__ char smraw[];
    __half* sA = (__half*)smraw;             // [128][LDA]
    __half* sB = sA + TM * LDA;              // [128][LDA]
    float*  sC = (float*)smraw;              // [128][132] overlay (epilogue)

    const int tid = threadIdx.x;
    const int wid = tid >> 5;
    const int wm = wid >> 2;                 // 0..1
    const int wn = wid & 3;                  // 0..3
    const int m0 = blockIdx.x * TM;
    const int n0 = blockIdx.y * TN;

    // Global-load mapping: 512 uint4 per operand tile, 2 per thread.
    // idx -> row = idx>>2, col8 = (idx&3)*8 halves (16B).
    const int r_ld = tid >> 1;               // 0..127
    const int c_ld = (tid & 1) * 16;         // 0 or 16 halves (two 16B chunks each)

    wmma::fragment<wmma::accumulator, 16, 16, 16, float> acc[4][2];
    #pragma unroll
    for (int i = 0; i < 4; i++)
        #pragma unroll
        for (int j = 0; j < 2; j++)
            wmma::fill_fragment(acc[i][j], 0.0f);

    // Prefetch first K-tile into registers
    uint4 pa[2], pb[2];
    {
        const __half* Ap = A + (size_t)(m0 + r_ld) * DD + c_ld;
        const __half* Bp = B + (size_t)(n0 + r_ld) * DD + c_ld;
        pa[0] = *(const uint4*)(Ap);     pa[1] = *(const uint4*)(Ap + 8);
        pb[0] = *(const uint4*)(Bp);     pb[1] = *(const uint4*)(Bp + 8);
    }

    for (int kt = 0; kt < NKT; kt++) {
        // Store prefetched tile to smem
        *(uint4*)&sA[r_ld * LDA + c_ld]     = pa[0];
        *(uint4*)&sA[r_ld * LDA + c_ld + 8] = pa[1];
        *(uint4*)&sB[r_ld * LDA + c_ld]     = pb[0];
        *(uint4*)&sB[r_ld * LDA + c_ld + 8] = pb[1];
        __syncthreads();

        // Prefetch next tile (overlaps with MMA below)
        if (kt + 1 < NKT) {
            const int k0 = (kt + 1) * TK;
            const __half* Ap = A + (size_t)(m0 + r_ld) * DD + k0 + c_ld;
            const __half* Bp = B + (size_t)(n0 + r_ld) * DD + k0 + c_ld;
            pa[0] = *(const uint4*)(Ap);     pa[1] = *(const uint4*)(Ap + 8);
            pb[0] = *(const uint4*)(Bp);     pb[1] = *(const uint4*)(Bp + 8);
        }

        #pragma unroll
        for (int kk = 0; kk < TK; kk += 16) {
            wmma::fragment<wmma::matrix_a, 16, 16, 16, __half, wmma::row_major> af[4];
            wmma::fragment<wmma::matrix_b, 16, 16, 16, __half, wmma::col_major> bf[2];
            #pragma unroll
            for (int i = 0; i < 4; i++)
                wmma::load_matrix_sync(af[i], &sA[(wm * 64 + i * 16) * LDA + kk], LDA);
            #pragma unroll
            for (int j = 0; j < 2; j++)
                wmma::load_matrix_sync(bf[j], &sB[(wn * 32 + j * 16) * LDA + kk], LDA);
            #pragma unroll
            for (int i = 0; i < 4; i++)
                #pragma unroll
                for (int j = 0; j < 2; j++)
                    wmma::mma_sync(acc[i][j], af[i], bf[j], acc[i][j]);
        }
        __syncthreads();   // before overwriting smem next iteration / epilogue
    }

    // Epilogue: stage fp32 C in smem, add bias, write coalesced
    #pragma unroll
    for (int i = 0; i < 4; i++)
        #pragma unroll
        for (int j = 0; j < 2; j++)
            wmma::store_matrix_sync(&sC[(wm * 64 + i * 16) * 132 + wn * 32 + j * 16],
                                    acc[i][j], 132, wmma::mem_row_major);
    __syncthreads();

    #pragma unroll
    for (int t = 0; t < 16; t++) {
        const int idx = tid + t * 256;       // 0..4095 float4s
        const int r = idx >> 5;              // 0..127
        const int c = (idx & 31) * 4;        // 0..124
        float4 cv = *(float4*)&sC[r * 132 + c];
        float4 bv = *(const float4*)(bias + n0 + c);
        cv.x += bv.x; cv.y += bv.y; cv.z += bv.z; cv.w += bv.w;
        *(float4*)(out + (size_t)(m0 + r) * DD + n0 + c) = cv;
    }
}

// ---------------------------------------------------------------------------
// Flash attention, causal, fp32. Q/K/V in plain [b,s,d]; head via +h*64.
// ---------------------------------------------------------------------------
#define ATILE 64
#define APAD  (ATILE + 4)
#define ATTN_SMEM (4 * 64 * APAD * 4)

__global__ __launch_bounds__(256)
void attn_kernel(const float* __restrict__ Q, const float* __restrict__ K,
                 const float* __restrict__ V, float* __restrict__ Oo)
{
    extern __shared__ float sm[];
    float (*sQt)[APAD] = (float(*)[APAD])(sm);
    float (*sKt)[APAD] = (float(*)[APAD])(sm + 1 * 64 * APAD);
    float (*sV )[APAD] = (float(*)[APAD])(sm + 2 * 64 * APAD);
    float (*sPt)[APAD] = (float(*)[APAD])(sm + 3 * 64 * APAD);

    const int tid = threadIdx.x;
    const int tx = tid & 15;
    const int ty = tid >> 4;
    const int qt = blockIdx.x;
    const int bh = blockIdx.y;
    const int b_ = bh / HH;
    const int h_ = bh % HH;

    const float* Qb = Q + (size_t)b_ * SS * DD + h_ * HDIM;
    const float* Kb = K + (size_t)b_ * SS * DD + h_ * HDIM;
    const float* Vb = V + (size_t)b_ * SS * DD + h_ * HDIM;

    #pragma unroll
    for (int l = 0; l < 4; l++) {
        const int lin = tid + l * 256;
        const int r = lin >> 4;
        const int d0 = (lin & 15) << 2;
        float4 v4 = *(const float4*)(Qb + (size_t)(qt * ATILE + r) * DD + d0);
        sQt[d0 + 0][r] = v4.x; sQt[d0 + 1][r] = v4.y;
        sQt[d0 + 2][r] = v4.z; sQt[d0 + 3][r] = v4.w;
    }

    float mrow[4], lrow[4], o[4][4];
    #pragma unroll
    for (int i = 0; i < 4; i++) {
        mrow[i] = -1e30f; lrow[i] = 0.0f;
        #pragma unroll
        for (int j = 0; j < 4; j++) o[i][j] = 0.0f;
    }

    for (int jt = 0; jt <= qt; jt++) {
        __syncthreads();
        #pragma unroll
        for (int l = 0; l < 4; l++) {
            const int lin = tid + l * 256;
            const int r = lin >> 4;
            const int d0 = (lin & 15) << 2;
            float4 kv = *(const float4*)(Kb + (size_t)(jt * ATILE + r) * DD + d0);
            sKt[d0 + 0][r] = kv.x; sKt[d0 + 1][r] = kv.y;
            sKt[d0 + 2][r] = kv.z; sKt[d0 + 3][r] = kv.w;
            *(float4*)&sV[r][d0] =
                *(const float4*)(Vb + (size_t)(jt * ATILE + r) * DD + d0);
        }
        __syncthreads();

        float sc[4][4] = {};
        #pragma unroll 16
        for (int dd = 0; dd < 64; dd++) {
            float4 a4 = *(float4*)&sQt[dd][ty << 2];
            float4 b4 = *(float4*)&sKt[dd][tx << 2];
            float ar[4] = {a4.x, a4.y, a4.z, a4.w};
            float br[4] = {b4.x, b4.y, b4.z, b4.w};
            #pragma unroll
            for (int i = 0; i < 4; i++)
                #pragma unroll
                for (int j = 0; j < 4; j++)
                    sc[i][j] += ar[i] * br[j];
        }

        const bool diag = (jt == qt);
        const float scale = 0.125f;

        #pragma unroll
        for (int i = 0; i < 4; i++) {
            float v[4];
            #pragma unroll
            for (int j = 0; j < 4; j++) {
                float val = sc[i][j] * scale;
                if (diag) {
                    const int qr = (ty << 2) + i;
                    const int kc = (tx << 2) + j;
                    if (kc > qr) val = -1e30f;
                }
                v[j] = val;
            }
            float tm = fmaxf(fmaxf(v[0], v[1]), fmaxf(v[2], v[3]));
            #pragma unroll
            for (int off = 8; off; off >>= 1)
                tm = fmaxf(tm, __shfl_xor_sync(0xffffffffu, tm, off));
            const float nm = fmaxf(mrow[i], tm);
            const float corr = __expf(mrow[i] - nm);
            float p[4], ps = 0.0f;
            #pragma unroll
            for (int j = 0; j < 4; j++) { p[j] = __expf(v[j] - nm); ps += p[j]; }
            #pragma unroll
            for (int off = 8; off; off >>= 1)
                ps += __shfl_xor_sync(0xffffffffu, ps, off);
            lrow[i] = lrow[i] * corr + ps;
            mrow[i] = nm;
            #pragma unroll
            for (int j = 0; j < 4; j++) o[i][j] *= corr;
            #pragma unroll
            for (int j = 0; j < 4; j++)
                sPt[(tx << 2) + j][(ty << 2) + i] = p[j];
        }
        __syncthreads();

        #pragma unroll 16
        for (int kk = 0; kk < 64; kk++) {
            float4 a4 = *(float4*)&sPt[kk][ty << 2];
            float4 b4 = *(float4*)&sV[kk][tx << 2];
            float ar[4] = {a4.x, a4.y, a4.z, a4.w};
            float br[4] = {b4.x, b4.y, b4.z, b4.w};
            #pragma unroll
            for (int i = 0; i < 4; i++)
                #pragma unroll
                for (int j = 0; j < 4; j++)
                    o[i][j] += ar[i] * br[j];
        }
    }

    #pragma unroll
    for (int i = 0; i < 4; i++) {
        const float inv = 1.0f / lrow[i];
        const int s_ = qt * ATILE + (ty << 2) + i;
        float4 ov = make_float4(o[i][0] * inv, o[i][1] * inv,
                                o[i][2] * inv, o[i][3] * inv);
        const size_t idx = ((size_t)(b_ * SS + s_)) * DD + h_ * HDIM + (tx << 2);
        *(float4*)(Oo + idx) = ov;
    }
}

// ---------------------------------------------------------------------------
// Launch
// ---------------------------------------------------------------------------
extern "C" void kernel_launch(void* const* d_in, const int* in_sizes, int n_in,
                              void* d_out, int out_size)
{
    (void)n_in; (void)in_sizes; (void)out_size;

    const float* x  = (const float*)d_in[0];
    const float* wq = (const float*)d_in[2];
    const float* bq = (const float*)d_in[3];
    const float* wk = (const float*)d_in[4];
    const float* bk = (const float*)d_in[5];
    const float* wv = (const float*)d_in[6];
    const float* bv = (const float*)d_in[7];
    const float* wo = (const float*)d_in[8];
    const float* bo = (const float*)d_in[9];
    float* out = (float*)d_out;

    static __half *xh = nullptr, *ah, *wqh, *wkh, *wvh, *woh;
    static float *q, *k, *v, *att;
    if (!xh) {
        cudaGetSymbolAddress((void**)&xh,  g_xh);
        cudaGetSymbolAddress((void**)&ah,  g_ah);
        cudaGetSymbolAddress((void**)&wqh, g_wqh);
        cudaGetSymbolAddress((void**)&wkh, g_wkh);
        cudaGetSymbolAddress((void**)&wvh, g_wvh);
        cudaGetSymbolAddress((void**)&woh, g_woh);
        cudaGetSymbolAddress((void**)&q,   g_q);
        cudaGetSymbolAddress((void**)&k,   g_k);
        cudaGetSymbolAddress((void**)&v,   g_v);
        cudaGetSymbolAddress((void**)&att, g_att);
        cudaFuncSetAttribute(gemm_wmma,
            cudaFuncAttributeMaxDynamicSharedMemorySize, GEMM_SMEM);
        cudaFuncSetAttribute(attn_kernel,
            cudaFuncAttributeMaxDynamicSharedMemorySize, ATTN_SMEM);
    }

    // fp16 conversions
    conv_half<<<NT * DD / 4 / 256, 256>>>(x, xh);
    dim3 wg(DD / 32, DD / 32);
    conv_wh<<<wg, 256>>>(wq, wqh);
    conv_wh<<<wg, 256>>>(wk, wkh);
    conv_wh<<<wg, 256>>>(wv, wvh);
    conv_wh<<<wg, 256>>>(wo, woh);

    // QKV projections (tensor cores via wmma)
    dim3 gg(NT / TM, DD / TN);   // 32 x 6
    gemm_wmma<<<gg, 256, GEMM_SMEM>>>(xh, wqh, bq, q);
    gemm_wmma<<<gg, 256, GEMM_SMEM>>>(xh, wkh, bk, k);
    gemm_wmma<<<gg, 256, GEMM_SMEM>>>(xh, wvh, bv, v);

    // Attention (fp32)
    dim3 ag(SS / ATILE, NBH);    // 32 x 24
    attn_kernel<<<ag, 256, ATTN_SMEM>>>(q, k, v, att);

    // Output projection
    conv_half<<<NT * DD / 4 / 256, 256>>>(att, ah);
    gemm_wmma<<<gg, 256, GEMM_SMEM>>>(ah, woh, bo, out);
}